// round 16
// baseline (speedup 1.0000x reference)
#include <cuda_runtime.h>
#include <math.h>

#define BB 64
#define TT 512
#define II 256
#define HH 512
#define CC 128

// Scratch (static device allocations are allowed; cudaMalloc is not)
__device__ float g_gates[(size_t)TT * BB * 4 * HH];   // [t][b][4H]  256 MB
__device__ float g_hs[(size_t)TT * BB * HH];          // [t][b][H]    64 MB
__device__ float g_h[2][BB * HH];                     // ping-pong h state

// Per-WARP flag barriers: 4 batch groups x 32 CTAs x 8 warps, each flag on
// its own 128-byte line. Warp w of CTA jg signals when its h columns
// {2w,2w+1} for step t are L2-visible.
__device__ unsigned int g_flags[4][32][8][32];
// One-shot full-grid barrier (replay-safe, generation counting) for init.
__device__ unsigned int g_bar_count;
__device__ unsigned int g_bar_gen;

__device__ __forceinline__ float sigmoidf_(float x) {
    return 1.0f / (1.0f + expf(-x));
}

// Packed dual-FMA: acc(lo,hi) += a(lo,hi) * b(lo,hi)   (ptxas never auto-fuses)
__device__ __forceinline__ void ffma2(unsigned long long& acc,
                                      unsigned long long a,
                                      unsigned long long b) {
    asm("fma.rn.f32x2 %0, %1, %2, %0;" : "+l"(acc) : "l"(a), "l"(b));
}

__device__ __forceinline__ unsigned long long pack2(float x) {
    unsigned long long r;
    asm("mov.b64 %0, {%1, %1};" : "=l"(r) : "f"(x));
    return r;
}

__device__ __forceinline__ float pairsum(unsigned long long v) {
    float2 f = *(float2*)&v;
    return f.x + f.y;
}

// Volatile L2 load/store for barrier flags (compiler must not hoist/CSE).
__device__ __forceinline__ unsigned int ldcg_u32v(const unsigned int* p) {
    unsigned int v;
    asm volatile("ld.global.cg.u32 %0, [%1];" : "=r"(v) : "l"(p));
    return v;
}
__device__ __forceinline__ void stcg_u32v(unsigned int* p, unsigned int v) {
    asm volatile("st.global.cg.u32 [%0], %1;" :: "l"(p), "r"(v) : "memory");
}
// Release store: cumulative over the happens-before established by the
// preceding __syncwarp()/__syncthreads(), so it releases the covered
// threads' prior stores.
__device__ __forceinline__ void strel_u32(unsigned int* p, unsigned int v) {
    asm volatile("st.global.release.gpu.u32 [%0], %1;" :: "l"(p), "r"(v) : "memory");
}

// ---------------------------------------------------------------------------
// Phase 1: G[t][b][n] = x[b][t][:] . W_ih[n][:] + b_ih[n] + b_hh[n]
// 128x128 tile, BK=8, double-buffered smem, fma.rn.f32x2. (R12, unchanged)
// ---------------------------------------------------------------------------
__global__ void __launch_bounds__(256) gates_gemm(
    const float* __restrict__ x,
    const float* __restrict__ W_ih,
    const float* __restrict__ b_ih,
    const float* __restrict__ b_hh)
{
    __shared__ float As[2][8][128];
    __shared__ float Bs[2][8][128];

    const int n0 = blockIdx.x * 128;
    const int m0 = blockIdx.y * 128;
    const int tid = threadIdx.x;
    const int tx = tid & 15;
    const int ty = tid >> 4;

    unsigned long long acc2[8][4];
#pragma unroll
    for (int i = 0; i < 8; i++)
#pragma unroll
        for (int j = 0; j < 4; j++) acc2[i][j] = 0ull;

    const int lr = tid >> 1;
    const int lk = (tid & 1) * 4;

    {
        float4 va = *(const float4*)(x + (size_t)(m0 + lr) * II + lk);
        float4 vb = *(const float4*)(W_ih + (size_t)(n0 + lr) * II + lk);
        As[0][lk + 0][lr] = va.x; As[0][lk + 1][lr] = va.y;
        As[0][lk + 2][lr] = va.z; As[0][lk + 3][lr] = va.w;
        Bs[0][lk + 0][lr] = vb.x; Bs[0][lk + 1][lr] = vb.y;
        Bs[0][lk + 2][lr] = vb.z; Bs[0][lk + 3][lr] = vb.w;
    }
    __syncthreads();

    const int NKB = II / 8;
    for (int kb = 0; kb < NKB; kb++) {
        const int cur = kb & 1;
        float4 na, nb;
        if (kb < NKB - 1) {
            int k0 = (kb + 1) * 8;
            na = *(const float4*)(x + (size_t)(m0 + lr) * II + k0 + lk);
            nb = *(const float4*)(W_ih + (size_t)(n0 + lr) * II + k0 + lk);
        }
#pragma unroll
        for (int k = 0; k < 8; k++) {
            float a[8];
            float4 a0 = *(const float4*)&As[cur][k][ty * 4];
            float4 a1 = *(const float4*)&As[cur][k][64 + ty * 4];
            ulonglong2 bp0 = *(const ulonglong2*)&Bs[cur][k][tx * 4];
            ulonglong2 bp1 = *(const ulonglong2*)&Bs[cur][k][64 + tx * 4];
            a[0]=a0.x; a[1]=a0.y; a[2]=a0.z; a[3]=a0.w;
            a[4]=a1.x; a[5]=a1.y; a[6]=a1.z; a[7]=a1.w;
#pragma unroll
            for (int i = 0; i < 8; i++) {
                unsigned long long a2 = pack2(a[i]);
                ffma2(acc2[i][0], a2, bp0.x);
                ffma2(acc2[i][1], a2, bp0.y);
                ffma2(acc2[i][2], a2, bp1.x);
                ffma2(acc2[i][3], a2, bp1.y);
            }
        }
        if (kb < NKB - 1) {
            const int nxt = cur ^ 1;
            As[nxt][lk + 0][lr] = na.x; As[nxt][lk + 1][lr] = na.y;
            As[nxt][lk + 2][lr] = na.z; As[nxt][lk + 3][lr] = na.w;
            Bs[nxt][lk + 0][lr] = nb.x; Bs[nxt][lk + 1][lr] = nb.y;
            Bs[nxt][lk + 2][lr] = nb.z; Bs[nxt][lk + 3][lr] = nb.w;
            __syncthreads();
        }
    }

#pragma unroll
    for (int i = 0; i < 8; i++) {
        int m = m0 + (i >> 2) * 64 + ty * 4 + (i & 3);
        int bb = m >> 9;
        int tt = m & 511;
        size_t row = ((size_t)tt * BB + bb) * (4 * HH);
#pragma unroll
        for (int j2 = 0; j2 < 4; j2++) {
            float2 f = *(float2*)&acc2[i][j2];
            int jlo = j2 * 2;
            int n0c = n0 + (jlo >> 2) * 64 + tx * 4 + (jlo & 3);
            g_gates[row + n0c]     = f.x + b_ih[n0c]     + b_hh[n0c];
            g_gates[row + n0c + 1] = f.y + b_ih[n0c + 1] + b_hh[n0c + 1];
        }
    }
}

// ---------------------------------------------------------------------------
// Phase 2: persistent recurrence, register-resident weights (R15 base).
// 128 CTAs (bg 0..3, jg 0..31) x 256 threads.
// R16 changes:
//  - PER-WARP flag release: reduce warp w's h-stores (columns {2w,2w+1}) are
//    warp-local, so after stcg: __syncwarp -> lane0 st.release of the warp's
//    own flag. The CTA-wide signal bar is DELETED.
//  - Consumer warp polls 32 producer-warp flags (4 CTAs x 8 warps), one per
//    lane, single ballot loop.
//  - psm double-buffered by t&1 (the deleted bar's other role). Same-buffer
//    reuse at t+2 is ordered by the remaining single bar.
//  -> exactly ONE CTA bar/step (psm visibility).
// Safety: compute(t+1) <= poll (all 32 producer-warp flags >= t+1) <= those
// warps finished reduce(t) <= passed bar(t) <= their CTA's stage reads of
// h[t] done => h[t+2] writes never race h[t] reads. Skew <= 1 step.
// ---------------------------------------------------------------------------
#define H_PITCH2 524                       // floats per staged h row
#define HSM_FLOATS (16 * H_PITCH2)         // 8384 floats = 33536 B
#define PSM_F4 (16 * 16 * 17)              // [kcc][jlc][b pad 17] = 69632 B
#define SMEM_RECUR (HSM_FLOATS * 4 + 2 * PSM_F4 * 16)   // 172800 B

__global__ void __launch_bounds__(256, 1) lstm_recur(const float* __restrict__ W_hh)
{
    extern __shared__ float smem[];
    float*  hsm  = smem;                                 // [16][H_PITCH2] linear
    float4* psm0 = (float4*)(smem + HSM_FLOATS);         // [(kcc*16+jlc)*17 + b]
    float4* psm1 = psm0 + PSM_F4;

    const int tid  = threadIdx.x;
    const int lane = tid & 31;
    const int wid  = tid >> 5;         // 0..7
    const int bl   = tid & 15;         // reduce-phase batch lane
    const int jl   = tid >> 4;         // reduce-phase unit lane
    const int kcc  = tid >> 4;         // compute-phase k-chunk (warp w: {2w,2w+1})
    const int jlc  = tid & 15;         // compute-phase unit lane
    const int bg   = blockIdx.x & 3;
    const int jg   = blockIdx.x >> 2;
    const int b    = bg * 16 + bl;
    const int j    = jg * 16 + jl;
    const int j0   = jg * 16;

    // W registers: 4 gates x 32 k-floats for unit (j0+jlc), cols kcc*32..
    ulonglong2 wreg[4][8];
#pragma unroll
    for (int g = 0; g < 4; g++) {
        const float* wrow = W_hh + ((size_t)(g * HH + j0 + jlc)) * HH + kcc * 32;
#pragma unroll
        for (int q = 0; q < 8; q++)
            wreg[g][q] = *(const ulonglong2*)(wrow + q * 4);
    }

    // init read-buffer h to 0 and reset this CTA's 8 warp flags
    __stcg(&g_h[0][b * HH + j], 0.0f);
    if (tid < 8) stcg_u32v(&g_flags[bg][jg][tid][0], 0u);
    float c = 0.0f;

    // One-shot full-grid barrier: orders h-zero + flag resets across ALL CTAs.
    __threadfence();
    __syncthreads();
    if (tid == 0) {
        unsigned int my = *((volatile unsigned int*)&g_bar_gen);
        unsigned int arrived = atomicAdd(&g_bar_count, 1u);
        if (arrived == (unsigned)gridDim.x - 1) {
            atomicExch(&g_bar_count, 0u);
            __threadfence();
            atomicAdd(&g_bar_gen, 1u);
        } else {
            while (*((volatile unsigned int*)&g_bar_gen) == my) { __nanosleep(32); }
        }
        __threadfence();
    }
    __syncthreads();

    // Initial stage of h[0] (zeros; grid barrier ordered the writes). Linear.
    {
        const float* hsrc = &g_h[0][(bg * 16) * HH];
#pragma unroll
        for (int i = 0; i < 8; i++) {
            int idx  = i * 256 + tid;
            int brow = idx >> 7;
            int k4   = idx & 127;
            float4 v = __ldcg((const float4*)(hsrc + (size_t)brow * HH) + k4);
            *(float4*)(hsm + brow * H_PITCH2 + k4 * 4) = v;
        }
    }
    // Preload gate inputs for t=0 (reduce identity bl,jl).
    const float* xgp = &g_gates[(size_t)b * (4 * HH) + j];
    float xi  = __ldcg(xgp);
    float xf  = __ldcg(xgp + HH);
    float xgg = __ldcg(xgp + 2 * HH);
    float xo  = __ldcg(xgp + 3 * HH);
    __syncthreads();

    // Consumer poll set: lane l watches producer CTA (4*wid + l>>3), warp l&7.
    const unsigned int* myflag = &g_flags[bg][4 * wid + (lane >> 3)][lane & 7][0];
    // Stage geometry: warp w covers k4 in [16w, 16w+16), rows 0..15.
    const int kbase = 16 * wid + (lane & 7);
    const int rbase = lane >> 3;            // 0..3

    for (int t = 0; t < TT; t++) {
        // ---- per-warp: poll own 32 producer-warp flags, stage own block ----
        if (t > 0) {
            unsigned int tgt = (unsigned int)t;
            while (true) {
                bool ok = (ldcg_u32v(myflag) >= tgt);
                if (__all_sync(0xffffffffu, ok)) break;
                __nanosleep(20);
            }
            __threadfence();   // acquire: order h reads after flag observe

            const float* hsrc = &g_h[t & 1][(bg * 16) * HH];
#pragma unroll
            for (int i = 0; i < 8; i++) {
                int brow = rbase + (i >> 1) * 4;    // 0..15
                int k4   = kbase + (i & 1) * 8;     // [16w, 16w+16)
                float4 v = __ldcg((const float4*)(hsrc + (size_t)brow * HH) + k4);
                *(float4*)(hsm + brow * H_PITCH2 + k4 * 4) = v;
            }
        }
        __syncwarp();   // stage(w) -> compute(w); hsm block is warp-private

        // ---- compute phase: thread (kcc, jlc); h reads are lane-broadcast ----
        float4* psm = (t & 1) ? psm1 : psm0;
        const float* hk = hsm + kcc * 32;
        float4* pout = &psm[(kcc * 16 + jlc) * 17];
#pragma unroll 2
        for (int bb = 0; bb < 16; bb++) {
            const float* hb = hk + bb * H_PITCH2;
            unsigned long long ai = 0ull, af = 0ull, ag = 0ull, ao = 0ull;
#pragma unroll
            for (int q = 0; q < 8; q++) {
                ulonglong2 h2 = *(const ulonglong2*)(hb + (q << 2));
                ffma2(ai, h2.x, wreg[0][q].x); ffma2(ai, h2.y, wreg[0][q].y);
                ffma2(af, h2.x, wreg[1][q].x); ffma2(af, h2.y, wreg[1][q].y);
                ffma2(ag, h2.x, wreg[2][q].x); ffma2(ag, h2.y, wreg[2][q].y);
                ffma2(ao, h2.x, wreg[3][q].x); ffma2(ao, h2.y, wreg[3][q].y);
            }
            float4 p;
            p.x = pairsum(ai); p.y = pairsum(af);
            p.z = pairsum(ag); p.w = pairsum(ao);
            pout[bb] = p;
        }
        __syncthreads();   // THE one bar: psm partials visible to all warps

        // ---- reduce phase: thread (bl, jl) ----
        float si = 0.f, sf = 0.f, sg = 0.f, so = 0.f;
#pragma unroll
        for (int kk = 0; kk < 16; kk++) {
            float4 p = psm[(kk * 16 + jl) * 17 + bl];
            si += p.x; sf += p.y; sg += p.z; so += p.w;
        }

        float gi = sigmoidf_(xi  + si);
        float gf = sigmoidf_(xf  + sf);
        float gg = tanhf    (xgg + sg);
        float go = sigmoidf_(xo  + so);
        c = gf * c + gi * gg;
        float hv = go * tanhf(c);
        __stcg(&g_h[(t + 1) & 1][b * HH + j], hv);

        if (t == TT - 1) {
            g_hs[((size_t)t * BB + b) * HH + j] = hv;
            break;
        }

        // ---- per-warp signal: syncwarp orders the warp's 32 h-stores into
        //      lane 0, whose release store publishes them ----
        __syncwarp();
        if (lane == 0) strel_u32(&g_flags[bg][jg][wid][0], (unsigned int)(t + 1));

        // History store + next-step gate prefetch ride the wait window.
        g_hs[((size_t)t * BB + b) * HH + j] = hv;
        {
            const float* xg = &g_gates[((size_t)(t + 1) * BB + b) * (4 * HH) + j];
            xi  = __ldcg(xg);
            xf  = __ldcg(xg + HH);
            xgg = __ldcg(xg + 2 * HH);
            xo  = __ldcg(xg + 3 * HH);
        }
    }
}

// ---------------------------------------------------------------------------
// Phase 3: out[b][t][c] = hs[t][b][:] . W_fc[c][:] + b_fc[c]  (unchanged)
// ---------------------------------------------------------------------------
__global__ void __launch_bounds__(256) fc_gemm(
    const float* __restrict__ W_fc,
    const float* __restrict__ b_fc,
    float* __restrict__ out)
{
    __shared__ float As[8][128];
    __shared__ float Bs[8][128];

    const int m0 = blockIdx.x * 128;
    const int tid = threadIdx.x;
    const int tx = tid & 15;
    const int ty = tid >> 4;

    float acc[8][8];
#pragma unroll
    for (int i = 0; i < 8; i++)
#pragma unroll
        for (int j = 0; j < 8; j++) acc[i][j] = 0.0f;

    const int lr = tid >> 1;
    const int lk = (tid & 1) * 4;

    for (int k0 = 0; k0 < HH; k0 += 8) {
        {
            float4 v = *(const float4*)(g_hs + (size_t)(m0 + lr) * HH + k0 + lk);
            As[lk + 0][lr] = v.x; As[lk + 1][lr] = v.y;
            As[lk + 2][lr] = v.z; As[lk + 3][lr] = v.w;
        }
        {
            float4 v = *(const float4*)(W_fc + (size_t)lr * HH + k0 + lk);
            Bs[lk + 0][lr] = v.x; Bs[lk + 1][lr] = v.y;
            Bs[lk + 2][lr] = v.z; Bs[lk + 3][lr] = v.w;
        }
        __syncthreads();
#pragma unroll
        for (int k = 0; k < 8; k++) {
            float a[8], b[8];
            float4 a0 = *(const float4*)&As[k][ty * 4];
            float4 a1 = *(const float4*)&As[k][64 + ty * 4];
            float4 b0 = *(const float4*)&Bs[k][tx * 4];
            float4 b1 = *(const float4*)&Bs[k][64 + tx * 4];
            a[0]=a0.x; a[1]=a0.y; a[2]=a0.z; a[3]=a0.w;
            a[4]=a1.x; a[5]=a1.y; a[6]=a1.z; a[7]=a1.w;
            b[0]=b0.x; b[1]=b0.y; b[2]=b0.z; b[3]=b0.w;
            b[4]=b1.x; b[5]=b1.y; b[6]=b1.z; b[7]=b1.w;
#pragma unroll
            for (int i = 0; i < 8; i++)
#pragma unroll
                for (int j = 0; j < 8; j++)
                    acc[i][j] = fmaf(a[i], b[j], acc[i][j]);
        }
        __syncthreads();
    }

#pragma unroll
    for (int i = 0; i < 8; i++) {
        int m = m0 + (i >> 2) * 64 + ty * 4 + (i & 3);
        int bb = m & 63;
        int tt = m >> 6;
        size_t orow = ((size_t)bb * TT + tt) * CC;
#pragma unroll
        for (int j = 0; j < 8; j++) {
            int cc = (j >> 2) * 64 + tx * 4 + (j & 3);
            out[orow + cc] = acc[i][j] + b_fc[cc];
        }
    }
}

// ---------------------------------------------------------------------------
extern "C" void kernel_launch(void* const* d_in, const int* in_sizes, int n_in,
                              void* d_out, int out_size)
{
    const float* x    = (const float*)d_in[0];
    const float* W_ih = (const float*)d_in[1];
    const float* W_hh = (const float*)d_in[2];
    const float* b_ih = (const float*)d_in[3];
    const float* b_hh = (const float*)d_in[4];
    const float* W_fc = (const float*)d_in[5];
    const float* b_fc = (const float*)d_in[6];
    float* out = (float*)d_out;

    cudaFuncSetAttribute(lstm_recur,
                         cudaFuncAttributeMaxDynamicSharedMemorySize,
                         SMEM_RECUR);

    dim3 g1(4 * HH / 128, (BB * TT) / 128);   // (16, 256)
    gates_gemm<<<g1, 256>>>(x, W_ih, b_ih, b_hh);

    lstm_recur<<<128, 256, SMEM_RECUR>>>(W_hh);   // 128 CTAs, co-resident

    fc_gemm<<<(BB * TT) / 128, 256>>>(W_fc, b_fc, out);
}

// round 17
// speedup vs baseline: 1.0785x; 1.0785x over previous
#include <cuda_runtime.h>
#include <math.h>

#define BB 64
#define TT 512
#define II 256
#define HH 512
#define CC 128

// Scratch (static device allocations are allowed; cudaMalloc is not)
__device__ float g_gates[(size_t)TT * BB * 4 * HH];   // [t][b][4H]  256 MB
__device__ float g_hs[(size_t)TT * BB * HH];          // [t][b][H]    64 MB
__device__ float g_h[2][BB * HH];                     // ping-pong h state

// Flag-array barriers: 4 batch groups x 32 CTA slots, each slot on its own
// 128-byte line (no atomic serialization, no shared-line contention).
__device__ unsigned int g_flags[4][32][32];
// One-shot full-grid barrier (replay-safe, generation counting) for init.
__device__ unsigned int g_bar_count;
__device__ unsigned int g_bar_gen;

// MUFU-based fast activations (ex2.approx + rcp.approx, ~1-2 ulp each;
// output error ~1e-6 -- 100x under the 1e-3 gate; NOT tanh.approx whose
// ~5e-4 error is too close to budget).
__device__ __forceinline__ float ex2a(float x) {
    float r; asm("ex2.approx.ftz.f32 %0, %1;" : "=f"(r) : "f"(x)); return r;
}
__device__ __forceinline__ float rcpa(float x) {
    float r; asm("rcp.approx.ftz.f32 %0, %1;" : "=f"(r) : "f"(x)); return r;
}
__device__ __forceinline__ float sigmoidf_(float x) {
    return rcpa(1.0f + ex2a(-1.4426950408889634f * x));
}
__device__ __forceinline__ float tanhf_(float x) {
    return fmaf(2.0f, rcpa(1.0f + ex2a(-2.8853900817779268f * x)), -1.0f);
}

// Packed dual-FMA: acc(lo,hi) += a(lo,hi) * b(lo,hi)   (ptxas never auto-fuses)
__device__ __forceinline__ void ffma2(unsigned long long& acc,
                                      unsigned long long a,
                                      unsigned long long b) {
    asm("fma.rn.f32x2 %0, %1, %2, %0;" : "+l"(acc) : "l"(a), "l"(b));
}

__device__ __forceinline__ unsigned long long pack2(float x) {
    unsigned long long r;
    asm("mov.b64 %0, {%1, %1};" : "=l"(r) : "f"(x));
    return r;
}

__device__ __forceinline__ float pairsum(unsigned long long v) {
    float2 f = *(float2*)&v;
    return f.x + f.y;
}

// Volatile L2 load/store for barrier flags (compiler must not hoist/CSE).
__device__ __forceinline__ unsigned int ldcg_u32v(const unsigned int* p) {
    unsigned int v;
    asm volatile("ld.global.cg.u32 %0, [%1];" : "=r"(v) : "l"(p));
    return v;
}
__device__ __forceinline__ void stcg_u32v(unsigned int* p, unsigned int v) {
    asm volatile("st.global.cg.u32 [%0], %1;" :: "l"(p), "r"(v) : "memory");
}
// Release store: cumulative over the CTA-scope happens-before established by
// the preceding __syncthreads(), so it releases ALL threads' prior stores.
__device__ __forceinline__ void strel_u32(unsigned int* p, unsigned int v) {
    asm volatile("st.global.release.gpu.u32 [%0], %1;" :: "l"(p), "r"(v) : "memory");
}

// ---------------------------------------------------------------------------
// Phase 1: G[t][b][n] = x[b][t][:] . W_ih[n][:] + b_ih[n] + b_hh[n]
// 128x128 tile, BK=8, double-buffered smem, fma.rn.f32x2. (R12, unchanged)
// ---------------------------------------------------------------------------
__global__ void __launch_bounds__(256) gates_gemm(
    const float* __restrict__ x,
    const float* __restrict__ W_ih,
    const float* __restrict__ b_ih,
    const float* __restrict__ b_hh)
{
    __shared__ float As[2][8][128];
    __shared__ float Bs[2][8][128];

    const int n0 = blockIdx.x * 128;
    const int m0 = blockIdx.y * 128;
    const int tid = threadIdx.x;
    const int tx = tid & 15;
    const int ty = tid >> 4;

    unsigned long long acc2[8][4];
#pragma unroll
    for (int i = 0; i < 8; i++)
#pragma unroll
        for (int j = 0; j < 4; j++) acc2[i][j] = 0ull;

    const int lr = tid >> 1;
    const int lk = (tid & 1) * 4;

    {
        float4 va = *(const float4*)(x + (size_t)(m0 + lr) * II + lk);
        float4 vb = *(const float4*)(W_ih + (size_t)(n0 + lr) * II + lk);
        As[0][lk + 0][lr] = va.x; As[0][lk + 1][lr] = va.y;
        As[0][lk + 2][lr] = va.z; As[0][lk + 3][lr] = va.w;
        Bs[0][lk + 0][lr] = vb.x; Bs[0][lk + 1][lr] = vb.y;
        Bs[0][lk + 2][lr] = vb.z; Bs[0][lk + 3][lr] = vb.w;
    }
    __syncthreads();

    const int NKB = II / 8;
    for (int kb = 0; kb < NKB; kb++) {
        const int cur = kb & 1;
        float4 na, nb;
        if (kb < NKB - 1) {
            int k0 = (kb + 1) * 8;
            na = *(const float4*)(x + (size_t)(m0 + lr) * II + k0 + lk);
            nb = *(const float4*)(W_ih + (size_t)(n0 + lr) * II + k0 + lk);
        }
#pragma unroll
        for (int k = 0; k < 8; k++) {
            float a[8];
            float4 a0 = *(const float4*)&As[cur][k][ty * 4];
            float4 a1 = *(const float4*)&As[cur][k][64 + ty * 4];
            ulonglong2 bp0 = *(const ulonglong2*)&Bs[cur][k][tx * 4];
            ulonglong2 bp1 = *(const ulonglong2*)&Bs[cur][k][64 + tx * 4];
            a[0]=a0.x; a[1]=a0.y; a[2]=a0.z; a[3]=a0.w;
            a[4]=a1.x; a[5]=a1.y; a[6]=a1.z; a[7]=a1.w;
#pragma unroll
            for (int i = 0; i < 8; i++) {
                unsigned long long a2 = pack2(a[i]);
                ffma2(acc2[i][0], a2, bp0.x);
                ffma2(acc2[i][1], a2, bp0.y);
                ffma2(acc2[i][2], a2, bp1.x);
                ffma2(acc2[i][3], a2, bp1.y);
            }
        }
        if (kb < NKB - 1) {
            const int nxt = cur ^ 1;
            As[nxt][lk + 0][lr] = na.x; As[nxt][lk + 1][lr] = na.y;
            As[nxt][lk + 2][lr] = na.z; As[nxt][lk + 3][lr] = na.w;
            Bs[nxt][lk + 0][lr] = nb.x; Bs[nxt][lk + 1][lr] = nb.y;
            Bs[nxt][lk + 2][lr] = nb.z; Bs[nxt][lk + 3][lr] = nb.w;
            __syncthreads();
        }
    }

#pragma unroll
    for (int i = 0; i < 8; i++) {
        int m = m0 + (i >> 2) * 64 + ty * 4 + (i & 3);
        int bb = m >> 9;
        int tt = m & 511;
        size_t row = ((size_t)tt * BB + bb) * (4 * HH);
#pragma unroll
        for (int j2 = 0; j2 < 4; j2++) {
            float2 f = *(float2*)&acc2[i][j2];
            int jlo = j2 * 2;
            int n0c = n0 + (jlo >> 2) * 64 + tx * 4 + (jlo & 3);
            g_gates[row + n0c]     = f.x + b_ih[n0c]     + b_hh[n0c];
            g_gates[row + n0c + 1] = f.y + b_ih[n0c + 1] + b_hh[n0c + 1];
        }
    }
}

// ---------------------------------------------------------------------------
// Phase 2: persistent recurrence, register-resident weights (R15, proven).
// 128 CTAs (bg 0..3, jg 0..31) x 256 threads. Warp-private hsm:
// warp w polls its own 4 producer flags, stages its own 4KB block
// (k4 in [16w,16w+16)), __syncwarp, computes with roles (kcc=tid>>4,
// jlc=tid&15) -- h reads lane-broadcast. psm single-buffer; 2 CTA bars/step.
// R17 change: MUFU fast activations only.
// ---------------------------------------------------------------------------
#define H_PITCH2 524                       // floats per staged h row
#define HSM_FLOATS (16 * H_PITCH2)         // 8384 floats = 33536 B
#define PSM_F4 (16 * 16 * 17)              // [kcc][jlc][b pad 17] = 69632 B
#define SMEM_RECUR (HSM_FLOATS * 4 + PSM_F4 * 16)

__global__ void __launch_bounds__(256, 1) lstm_recur(const float* __restrict__ W_hh)
{
    extern __shared__ float smem[];
    float*  hsm = smem;                                 // [16][H_PITCH2] linear
    float4* psm = (float4*)(smem + HSM_FLOATS);         // [(kcc*16+jlc)*17 + b]

    const int tid  = threadIdx.x;
    const int lane = tid & 31;
    const int wid  = tid >> 5;         // 0..7
    const int bl   = tid & 15;         // reduce-phase batch lane
    const int jl   = tid >> 4;         // reduce-phase unit lane
    const int kcc  = tid >> 4;         // compute-phase k-chunk (warp w: {2w,2w+1})
    const int jlc  = tid & 15;         // compute-phase unit lane
    const int bg   = blockIdx.x & 3;
    const int jg   = blockIdx.x >> 2;
    const int b    = bg * 16 + bl;
    const int j    = jg * 16 + jl;
    const int j0   = jg * 16;

    // W registers: 4 gates x 32 k-floats for unit (j0+jlc), cols kcc*32..
    ulonglong2 wreg[4][8];
#pragma unroll
    for (int g = 0; g < 4; g++) {
        const float* wrow = W_hh + ((size_t)(g * HH + j0 + jlc)) * HH + kcc * 32;
#pragma unroll
        for (int q = 0; q < 8; q++)
            wreg[g][q] = *(const ulonglong2*)(wrow + q * 4);
    }

    // init read-buffer h to 0 and reset our flag slot (fresh every replay)
    __stcg(&g_h[0][b * HH + j], 0.0f);
    if (tid == 0) stcg_u32v(&g_flags[bg][jg][0], 0u);
    float c = 0.0f;

    // One-shot full-grid barrier: orders h-zero + flag resets across ALL CTAs.
    __threadfence();
    __syncthreads();
    if (tid == 0) {
        unsigned int my = *((volatile unsigned int*)&g_bar_gen);
        unsigned int arrived = atomicAdd(&g_bar_count, 1u);
        if (arrived == (unsigned)gridDim.x - 1) {
            atomicExch(&g_bar_count, 0u);
            __threadfence();
            atomicAdd(&g_bar_gen, 1u);
        } else {
            while (*((volatile unsigned int*)&g_bar_gen) == my) { __nanosleep(32); }
        }
        __threadfence();
    }
    __syncthreads();

    // Initial stage of h[0] (zeros; grid barrier ordered the writes). Linear.
    {
        const float* hsrc = &g_h[0][(bg * 16) * HH];
#pragma unroll
        for (int i = 0; i < 8; i++) {
            int idx  = i * 256 + tid;
            int brow = idx >> 7;
            int k4   = idx & 127;
            float4 v = __ldcg((const float4*)(hsrc + (size_t)brow * HH) + k4);
            *(float4*)(hsm + brow * H_PITCH2 + k4 * 4) = v;
        }
    }
    // Preload gate inputs for t=0 (reduce identity bl,jl).
    const float* xgp = &g_gates[(size_t)b * (4 * HH) + j];
    float xi  = __ldcg(xgp);
    float xf  = __ldcg(xgp + HH);
    float xgg = __ldcg(xgp + 2 * HH);
    float xo  = __ldcg(xgp + 3 * HH);
    __syncthreads();

    // This warp's producer flag (lanes 0..3 poll CTAs 4*wid + lane).
    const unsigned int* myflag = &g_flags[bg][4 * wid + (lane & 3)][0];
    // Stage geometry: warp w covers k4 in [16w, 16w+16), rows 0..15.
    const int kbase = 16 * wid + (lane & 7);
    const int rbase = lane >> 3;            // 0..3

    for (int t = 0; t < TT; t++) {
        // ---- per-warp: poll own 4 flags, stage own block (t>0) ----
        if (t > 0) {
            unsigned int tgt = (unsigned int)t;
            while (true) {
                bool ok = (lane >= 4) || (ldcg_u32v(myflag) >= tgt);
                if (__all_sync(0xffffffffu, ok)) break;
                __nanosleep(20);
            }
            __threadfence();   // acquire: order h reads after flag observe

            const float* hsrc = &g_h[t & 1][(bg * 16) * HH];
#pragma unroll
            for (int i = 0; i < 8; i++) {
                int brow = rbase + (i >> 1) * 4;    // 0..15
                int k4   = kbase + (i & 1) * 8;     // [16w, 16w+16)
                float4 v = __ldcg((const float4*)(hsrc + (size_t)brow * HH) + k4);
                *(float4*)(hsm + brow * H_PITCH2 + k4 * 4) = v;
            }
        }
        __syncwarp();   // stage(w) -> compute(w); hsm block is warp-private

        // ---- compute phase: thread (kcc, jlc); h reads are lane-broadcast ----
        const float* hk = hsm + kcc * 32;
        float4* pout = &psm[(kcc * 16 + jlc) * 17];
#pragma unroll 2
        for (int bb = 0; bb < 16; bb++) {
            const float* hb = hk + bb * H_PITCH2;
            unsigned long long ai = 0ull, af = 0ull, ag = 0ull, ao = 0ull;
#pragma unroll
            for (int q = 0; q < 8; q++) {
                ulonglong2 h2 = *(const ulonglong2*)(hb + (q << 2));
                ffma2(ai, h2.x, wreg[0][q].x); ffma2(ai, h2.y, wreg[0][q].y);
                ffma2(af, h2.x, wreg[1][q].x); ffma2(af, h2.y, wreg[1][q].y);
                ffma2(ag, h2.x, wreg[2][q].x); ffma2(ag, h2.y, wreg[2][q].y);
                ffma2(ao, h2.x, wreg[3][q].x); ffma2(ao, h2.y, wreg[3][q].y);
            }
            float4 p;
            p.x = pairsum(ai); p.y = pairsum(af);
            p.z = pairsum(ag); p.w = pairsum(ao);
            pout[bb] = p;
        }
        __syncthreads();   // psm partials visible (cross-warp consumers)

        // ---- reduce phase: thread (bl, jl) ----
        float si = 0.f, sf = 0.f, sg = 0.f, so = 0.f;
#pragma unroll
        for (int kk = 0; kk < 16; kk++) {
            float4 p = psm[(kk * 16 + jl) * 17 + bl];
            si += p.x; sf += p.y; sg += p.z; so += p.w;
        }

        float gi = sigmoidf_(xi  + si);
        float gf = sigmoidf_(xf  + sf);
        float gg = tanhf_   (xgg + sg);
        float go = sigmoidf_(xo  + so);
        c = gf * c + gi * gg;
        float hv = go * tanhf_(c);
        __stcg(&g_h[(t + 1) & 1][b * HH + j], hv);

        if (t == TT - 1) {
            g_hs[((size_t)t * BB + b) * HH + j] = hv;
            break;
        }

        // ---- signal: CTA-sync (h stores + psm reads done), tid0 release ----
        __syncthreads();
        if (tid == 0) strel_u32(&g_flags[bg][jg][0], (unsigned int)(t + 1));

        // History store + next-step gate prefetch ride the wait window.
        g_hs[((size_t)t * BB + b) * HH + j] = hv;
        {
            const float* xg = &g_gates[((size_t)(t + 1) * BB + b) * (4 * HH) + j];
            xi  = __ldcg(xg);
            xf  = __ldcg(xg + HH);
            xgg = __ldcg(xg + 2 * HH);
            xo  = __ldcg(xg + 3 * HH);
        }
    }
}

// ---------------------------------------------------------------------------
// Phase 3: out[b][t][c] = hs[t][b][:] . W_fc[c][:] + b_fc[c]  (unchanged)
// ---------------------------------------------------------------------------
__global__ void __launch_bounds__(256) fc_gemm(
    const float* __restrict__ W_fc,
    const float* __restrict__ b_fc,
    float* __restrict__ out)
{
    __shared__ float As[8][128];
    __shared__ float Bs[8][128];

    const int m0 = blockIdx.x * 128;
    const int tid = threadIdx.x;
    const int tx = tid & 15;
    const int ty = tid >> 4;

    float acc[8][8];
#pragma unroll
    for (int i = 0; i < 8; i++)
#pragma unroll
        for (int j = 0; j < 8; j++) acc[i][j] = 0.0f;

    const int lr = tid >> 1;
    const int lk = (tid & 1) * 4;

    for (int k0 = 0; k0 < HH; k0 += 8) {
        {
            float4 v = *(const float4*)(g_hs + (size_t)(m0 + lr) * HH + k0 + lk);
            As[lk + 0][lr] = v.x; As[lk + 1][lr] = v.y;
            As[lk + 2][lr] = v.z; As[lk + 3][lr] = v.w;
        }
        {
            float4 v = *(const float4*)(W_fc + (size_t)lr * HH + k0 + lk);
            Bs[lk + 0][lr] = v.x; Bs[lk + 1][lr] = v.y;
            Bs[lk + 2][lr] = v.z; Bs[lk + 3][lr] = v.w;
        }
        __syncthreads();
#pragma unroll
        for (int k = 0; k < 8; k++) {
            float a[8], b[8];
            float4 a0 = *(const float4*)&As[k][ty * 4];
            float4 a1 = *(const float4*)&As[k][64 + ty * 4];
            float4 b0 = *(const float4*)&Bs[k][tx * 4];
            float4 b1 = *(const float4*)&Bs[k][64 + tx * 4];
            a[0]=a0.x; a[1]=a0.y; a[2]=a0.z; a[3]=a0.w;
            a[4]=a1.x; a[5]=a1.y; a[6]=a1.z; a[7]=a1.w;
            b[0]=b0.x; b[1]=b0.y; b[2]=b0.z; b[3]=b0.w;
            b[4]=b1.x; b[5]=b1.y; b[6]=b1.z; b[7]=b1.w;
#pragma unroll
            for (int i = 0; i < 8; i++)
#pragma unroll
                for (int j = 0; j < 8; j++)
                    acc[i][j] = fmaf(a[i], b[j], acc[i][j]);
        }
        __syncthreads();
    }

#pragma unroll
    for (int i = 0; i < 8; i++) {
        int m = m0 + (i >> 2) * 64 + ty * 4 + (i & 3);
        int bb = m & 63;
        int tt = m >> 6;
        size_t orow = ((size_t)bb * TT + tt) * CC;
#pragma unroll
        for (int j = 0; j < 8; j++) {
            int cc = (j >> 2) * 64 + tx * 4 + (j & 3);
            out[orow + cc] = acc[i][j] + b_fc[cc];
        }
    }
}

// ---------------------------------------------------------------------------
extern "C" void kernel_launch(void* const* d_in, const int* in_sizes, int n_in,
                              void* d_out, int out_size)
{
    const float* x    = (const float*)d_in[0];
    const float* W_ih = (const float*)d_in[1];
    const float* W_hh = (const float*)d_in[2];
    const float* b_ih = (const float*)d_in[3];
    const float* b_hh = (const float*)d_in[4];
    const float* W_fc = (const float*)d_in[5];
    const float* b_fc = (const float*)d_in[6];
    float* out = (float*)d_out;

    cudaFuncSetAttribute(lstm_recur,
                         cudaFuncAttributeMaxDynamicSharedMemorySize,
                         SMEM_RECUR);

    dim3 g1(4 * HH / 128, (BB * TT) / 128);   // (16, 256)
    gates_gemm<<<g1, 256>>>(x, W_ih, b_ih, b_hh);

    lstm_recur<<<128, 256, SMEM_RECUR>>>(W_hh);   // 128 CTAs, co-resident

    fc_gemm<<<(BB * TT) / 128, 256>>>(W_fc, b_fc, out);
}